// round 9
// baseline (speedup 1.0000x reference)
#include <cuda_runtime.h>
#include <math.h>

#define B 64
#define CHI 20
#define D 65536                 // 64*32*32 floats per frame
#define D4 (D / 4)

#define NGROUPS 16              // concurrent batches (16 * 5.24 MB = 84 MB < L2)
#define GBLK 16                 // blocks per group
#define NITER (B / NGROUPS)     // 4 batches per group, sequential
#define NBLK (NGROUPS * GBLK)   // 256 blocks, all co-resident in one wave
#define CHUNK4 (D4 / GBLK)      // 1024 float4 per frame per block (phase 1)
#define TILES2 (D / (GBLK * 256))  // 16 phase-2 sub-tiles per block

__device__ float g_partial[B * CHI * GBLK];     // per-block partial dots
__device__ unsigned g_bar[NGROUPS * NITER];     // group barrier counters

__global__ void init_kernel() {
    if (threadIdx.x < NGROUPS * NITER) g_bar[threadIdx.x] = 0u;
}

// ---------------------------------------------------------------------------
// Fused persistent kernel. Group g (GBLK blocks) processes batches
// b = it*NGROUPS + g for it = 0..3:
//   phase 1: scores partials over this block's D/16 chunk (frames view, coalesced)
//   group barrier (release/acquire via global atomic + spin; all blocks resident)
//   softmax recomputed per block from partials (L2-hot, tiny)
//   phase 2: out[b,d] = sum_c x_flat[b, d*CHI + c] * alpha[c]  via SMEM staging
//            -- reads the 5.24 MB batch that phase 1 just installed in L2.
// ---------------------------------------------------------------------------
__global__ __launch_bounds__(256) void fused_kernel(const float* __restrict__ x,
                                                    float* __restrict__ out) {
    const int g   = blockIdx.x / GBLK;
    const int j   = blockIdx.x % GBLK;
    const int tid = threadIdx.x;
    const int warp = tid >> 5;
    const int lane = tid & 31;

    __shared__ float4 s4[256 * CHI / 4];   // 20 KB staging
    __shared__ float sred[CHI][8];
    __shared__ float s_alpha[CHI];

    for (int it = 0; it < NITER; it++) {
        const int b = it * NGROUPS + g;
        const float* __restrict__ xb = x + (size_t)b * CHI * D;

        // ------------------ phase 1: score partials ------------------
        const float4* __restrict__ xb4 =
            reinterpret_cast<const float4*>(xb) + (size_t)j * CHUNK4;

        float acc[CHI];
        #pragma unroll
        for (int c = 0; c < CHI; c++) acc[c] = 0.0f;

        #pragma unroll
        for (int i = 0; i < CHUNK4 / 256; i++) {   // 4 iterations
            const int idx = i * 256 + tid;
            const float4 l = xb4[(size_t)(CHI - 1) * D4 + idx];
            #pragma unroll
            for (int c = 0; c < CHI - 1; c++) {
                const float4 f = xb4[(size_t)c * D4 + idx];
                acc[c] = fmaf(f.x, l.x, fmaf(f.y, l.y,
                         fmaf(f.z, l.z, fmaf(f.w, l.w, acc[c]))));
            }
            acc[CHI - 1] = fmaf(l.x, l.x, fmaf(l.y, l.y,
                           fmaf(l.z, l.z, fmaf(l.w, l.w, acc[CHI - 1]))));
        }

        #pragma unroll
        for (int c = 0; c < CHI; c++) {
            #pragma unroll
            for (int o = 16; o; o >>= 1)
                acc[c] += __shfl_xor_sync(0xFFFFFFFFu, acc[c], o);
        }
        if (lane == 0) {
            #pragma unroll
            for (int c = 0; c < CHI; c++) sred[c][warp] = acc[c];
        }
        __syncthreads();
        if (tid < CHI) {
            float v = 0.0f;
            #pragma unroll
            for (int w = 0; w < 8; w++) v += sred[tid][w];
            g_partial[(b * CHI + tid) * GBLK + j] = v;
        }
        __threadfence();           // release partials
        __syncthreads();

        // ------------------ group barrier ------------------
        if (tid == 0) {
            unsigned* ctr = &g_bar[g * NITER + it];
            atomicAdd(ctr, 1u);
            while (*(volatile unsigned*)ctr < (unsigned)GBLK) __nanosleep(64);
            __threadfence();       // acquire
        }
        __syncthreads();

        // ------------------ softmax (warp 0, then broadcast) ------------------
        if (warp == 0) {
            float s = -INFINITY;
            if (lane < CHI) {
                const float* p = &g_partial[(b * CHI + lane) * GBLK];
                float t = 0.0f;
                #pragma unroll
                for (int k = 0; k < GBLK; k++) t += p[k];
                s = t * (1.0f / CHI);
            }
            float m = s;
            #pragma unroll
            for (int o = 16; o; o >>= 1)
                m = fmaxf(m, __shfl_xor_sync(0xFFFFFFFFu, m, o));
            float e = (lane < CHI) ? expf(s - m) : 0.0f;
            float sum = e;
            #pragma unroll
            for (int o = 16; o; o >>= 1)
                sum += __shfl_xor_sync(0xFFFFFFFFu, sum, o);
            if (lane < CHI) s_alpha[lane] = e / sum;
        }
        __syncthreads();

        float a[CHI];
        #pragma unroll
        for (int c = 0; c < CHI; c++) a[c] = s_alpha[c];

        // ------------------ phase 2: out (L2-hot read) ------------------
        #pragma unroll 1
        for (int t = 0; t < TILES2; t++) {        // 16 sub-tiles of 256 d's
            const int dbase = (j * TILES2 + t) * 256;
            const float4* __restrict__ src =
                reinterpret_cast<const float4*>(xb + (size_t)dbase * CHI);
            #pragma unroll
            for (int i = 0; i < 5; i++)
                s4[i * 256 + tid] = src[i * 256 + tid];
            __syncthreads();

            const float4* mine = s4 + tid * 5;    // 20 contiguous floats
            float o_ = 0.0f;
            #pragma unroll
            for (int i = 0; i < 5; i++) {
                const float4 v = mine[i];
                o_ = fmaf(v.x, a[4 * i + 0], fmaf(v.y, a[4 * i + 1],
                     fmaf(v.z, a[4 * i + 2], fmaf(v.w, a[4 * i + 3], o_))));
            }
            out[(size_t)b * D + dbase + tid] = o_;
            __syncthreads();
        }
    }
}

extern "C" void kernel_launch(void* const* d_in, const int* in_sizes, int n_in,
                              void* d_out, int out_size) {
    const float* x = (const float*)d_in[0];
    float* out = (float*)d_out;

    init_kernel<<<1, 64>>>();
    fused_kernel<<<NBLK, 256>>>(x, out);
}